// round 10
// baseline (speedup 1.0000x reference)
#include <cuda_runtime.h>
#include <cuda_fp16.h>
#include <cstdint>
#include <math.h>

#define B_SZ 2048
#define T_SZ 128
#define F_SZ 64
#define H_SZ 512
#define NSTG 3
#define KC   64                               // k halves per chunk
#define STAGE_BYTES (2 * 128 * 128)           // A(16KB) + B(16KB) fp16
#define SMEM_DYN (NSTG * STAGE_BYTES)         // 96 KB
#define NCTA 256
#define NGRP 16
#define GSTR 32                               // barrier stride (128B)

// ---------------------------------------------------------------------------
// Device scratch
// ---------------------------------------------------------------------------
__device__ __align__(128) __half g_h1[2][B_SZ * H_SZ];
__device__ __align__(128) float  g_c1[B_SZ * H_SZ];
__device__ __align__(128) __half g_h2[2][B_SZ * H_SZ];
__device__ __align__(128) float  g_c2[B_SZ * H_SZ];
__device__ __align__(128) __half g_x16[B_SZ * T_SZ * F_SZ];
// Pre-transposed, gate-permuted fp16 weights, n-major: dst[n][k].
// permuted n -> gate g=(n>>4)&3, j=(n>>6)*16+(n&15); orig col = g*512 + j
__device__ __align__(128) __half g_Wt1[2048 * 64];
__device__ __align__(128) __half g_Ut1[2048 * 512];
__device__ __align__(128) __half g_Wt2[2048 * 512];
__device__ __align__(128) __half g_Ut2[2048 * 512];
__device__ __align__(128) float  g_bp1[2048];
__device__ __align__(128) float  g_bp2[2048];
// Per-row-group barrier state (reset by init kernel each launch/replay)
__device__ unsigned g_garr[NGRP * GSTR];
__device__ unsigned g_gep[NGRP * GSTR];

// ---------------------------------------------------------------------------
// Helpers
// ---------------------------------------------------------------------------
__device__ __forceinline__ uint32_t smem_u32(const void* p) {
    uint32_t a;
    asm("{ .reg .u64 t; cvta.to.shared.u64 t, %1; cvt.u32.u64 %0, t; }" : "=r"(a) : "l"(p));
    return a;
}

#define CP_ASYNC16(dst, src) \
    asm volatile("cp.async.cg.shared.global [%0], [%1], 16;" :: "r"(dst), "l"(src) : "memory")
#define CP_ASYNC_COMMIT() asm volatile("cp.async.commit_group;" ::: "memory")
#define CP_ASYNC_WAIT(n)  asm volatile("cp.async.wait_group %0;" :: "n"(n) : "memory")

#define LDSM4(r0, r1, r2, r3, addr)                                           \
    asm volatile("ldmatrix.sync.aligned.m8n8.x4.shared.b16 {%0,%1,%2,%3}, [%4];" \
        : "=r"(r0), "=r"(r1), "=r"(r2), "=r"(r3) : "r"(addr))

#define MMA_F16(c, a, b)                                                      \
    asm volatile("mma.sync.aligned.m16n8k16.row.col.f32.f16.f16.f32 "         \
        "{%0,%1,%2,%3}, {%4,%5,%6,%7}, {%8,%9}, {%0,%1,%2,%3};"               \
        : "+f"((c)[0]), "+f"((c)[1]), "+f"((c)[2]), "+f"((c)[3])              \
        : "r"((a)[0]), "r"((a)[1]), "r"((a)[2]), "r"((a)[3]),                 \
          "r"((b)[0]), "r"((b)[1]))

__device__ __forceinline__ unsigned ld_acq(const unsigned* p) {
    unsigned v;
    asm volatile("ld.acquire.gpu.u32 %0, [%1];" : "=r"(v) : "l"(p));
    return v;
}

// Row-group barrier: 16 CTAs sharing the same batch-row block. Safe: all
// NCTA CTAs are co-resident (256 <= 2/SM * 148).
__device__ __forceinline__ void group_bar(int gI, unsigned target) {
    __syncthreads();
    if (threadIdx.x == 0) {
        __threadfence();
        unsigned a = atomicAdd(&g_garr[gI * GSTR], 1u);
        if (a == 15u) {
            g_garr[gI * GSTR] = 0u;
            __threadfence();
            atomicAdd(&g_gep[gI * GSTR], 1u);
        } else {
            while (ld_acq(&g_gep[gI * GSTR]) < target) __nanosleep(32);
        }
    }
    __syncthreads();
}

// ---------------------------------------------------------------------------
// Init / prep kernels
// ---------------------------------------------------------------------------
__global__ void init_state_kernel() {
    int idx = blockIdx.x * blockDim.x + threadIdx.x;
    if (idx < NGRP * GSTR) { g_garr[idx] = 0u; g_gep[idx] = 0u; }
    if (idx < B_SZ * H_SZ) {
        g_h1[1][idx] = __float2half(0.f);
        g_h2[1][idx] = __float2half(0.f);
        g_c1[idx] = 0.f; g_c2[idx] = 0.f;
    }
}

__global__ void convert_x(const float* __restrict__ x) {
    int idx = blockIdx.x * 256 + threadIdx.x;   // exact grid
    g_x16[idx] = __float2half(x[idx]);
}

__global__ void transpose_wu(const float* __restrict__ src, int K, int which) {
    __half* dst = (which == 0) ? g_Wt1 : (which == 1) ? g_Ut1
                : (which == 2) ? g_Wt2 : g_Ut2;
    int idx = blockIdx.x * 256 + threadIdx.x;   // exact grid: 2048*K
    int n = idx / K, k = idx - n * K;
    int orig = ((n >> 4) & 3) * 512 + (n >> 6) * 16 + (n & 15);
    dst[idx] = __float2half(src[(size_t)k * 2048 + orig]);
}

__global__ void permute_bias(const float* __restrict__ b, int which) {
    float* dst = (which == 0) ? g_bp1 : g_bp2;
    int n = blockIdx.x * 256 + threadIdx.x;
    dst[n] = b[((n >> 4) & 3) * 512 + (n >> 6) * 16 + (n & 15)];
}

// ---------------------------------------------------------------------------
// Tile descriptor + chunk loader
// ---------------------------------------------------------------------------
struct Tile {
    const __half* A1; const __half* A2;
    const __half* B1; const __half* B2;
    unsigned sA1;          // A1 row stride in halves
    int NC1; int BK1;      // chunks in first K-segment; B1 row stride
    const float* sbias;
    float* cst; __half* hout;
};

__device__ __forceinline__ void load_chunk_t(
    const Tile& T, int c, uint32_t stBase, int tid, int rb, int cb)
{
    const __half* Asrc; unsigned sA; const __half* Bsrc; int BK; int kloc;
    if (c < T.NC1) { Asrc = T.A1; sA = T.sA1; Bsrc = T.B1; BK = T.BK1; kloc = c * KC; }
    else           { Asrc = T.A2; sA = H_SZ;  Bsrc = T.B2; BK = H_SZ;  kloc = (c - T.NC1) * KC; }

    const int r  = tid >> 1;            // 0..127
    const int cq = (tid & 1) * 4;       // 16B-chunk 0..3 or 4..7
    const uint32_t aS = stBase;
    const uint32_t bS = stBase + 16384;

    const __half* ag = Asrc + (size_t)(rb + r) * sA + kloc + cq * 8;
    const __half* bg = Bsrc + (size_t)(cb + r) * BK + kloc + cq * 8;
    const uint32_t rowoff = (uint32_t)r << 7;
#pragma unroll
    for (int q = 0; q < 4; ++q) {
        uint32_t sw = (uint32_t)((cq + q) ^ (r & 7)) << 4;
        CP_ASYNC16(aS + rowoff + sw, ag + q * 8);
        CP_ASYNC16(bS + rowoff + sw, bg + q * 8);
    }
    CP_ASYNC_COMMIT();
}

// ---------------------------------------------------------------------------
// Consume one tile from the continuous per-interval chunk stream.
// Schedule per chunk: wait(chunk ready) -> sync -> issue chunk gc+2 -> compute.
// Single __syncthreads per chunk; overwrite-safety: stage (gc+2)%3 was
// consumed at iteration gc-1, and this iteration's sync proves all warps
// finished it.
// ---------------------------------------------------------------------------
template <typename F>
__device__ void consume_tile(
    const Tile& T, int gcBase, int NC, int ntot, F&& issue,
    uint32_t base, int tid, int rb, int cbI)
{
    const int lane = tid & 31;
    const int warp = tid >> 5;
    const int wm   = warp >> 1;
    const int wn   = warp & 1;

    float acc[2][8][4];
#pragma unroll
    for (int mi = 0; mi < 2; ++mi)
#pragma unroll
        for (int nf = 0; nf < 8; ++nf)
#pragma unroll
            for (int e = 0; e < 4; ++e) acc[mi][nf][e] = 0.f;

    const int lrow = lane & 7;
    const int lm   = lane >> 3;
    const uint32_t arow   = (uint32_t)(wm * 32 + (lm & 1) * 8 + lrow);
    const int      ach    = lm >> 1;
    const uint32_t bnrow0 = (uint32_t)(wn * 64 + (lm >> 1) * 8 + lrow);
    const int      bch    = lm & 1;

    for (int c = 0; c < NC; ++c) {
        const int gc = gcBase + c;
        // wait: groups complete in order; after this, chunk gc is resident.
        if (gc == ntot - 1) CP_ASYNC_WAIT(0);
        else                CP_ASYNC_WAIT(1);
        __syncthreads();
        issue(gc + 2);

        const uint32_t aS = base + (gc % NSTG) * STAGE_BYTES;
        const uint32_t bS = aS + 16384;
#pragma unroll
        for (int ks = 0; ks < 4; ++ks) {
            const int c0 = ks * 2;
            uint32_t afr[2][4];
#pragma unroll
            for (int mi = 0; mi < 2; ++mi) {
                uint32_t ad = aS + ((arow + mi * 16) << 7)
                            + ((uint32_t)((c0 + ach) ^ lrow) << 4);
                LDSM4(afr[mi][0], afr[mi][1], afr[mi][2], afr[mi][3], ad);
            }
            uint32_t bfr[8][2];
#pragma unroll
            for (int j = 0; j < 4; ++j) {
                uint32_t bd = bS + ((bnrow0 + j * 16) << 7)
                            + ((uint32_t)((c0 + bch) ^ lrow) << 4);
                LDSM4(bfr[2 * j][0], bfr[2 * j][1],
                      bfr[2 * j + 1][0], bfr[2 * j + 1][1], bd);
            }
#pragma unroll
            for (int mi = 0; mi < 2; ++mi)
#pragma unroll
                for (int nf = 0; nf < 8; ++nf)
                    MMA_F16(acc[mi][nf], afr[mi], bfr[nf]);
        }
    }

    // ---- LSTM epilogue (overlaps with next tile's in-flight loads) --------
    const int kq = lane & 3;
    const int rA = lane >> 2;
    const int jgbase = (cbI * 2 + wn) * 16;
#pragma unroll
    for (int mi = 0; mi < 2; ++mi) {
#pragma unroll
        for (int ri = 0; ri < 2; ++ri) {
            const int row = rb + wm * 32 + mi * 16 + rA + ri * 8;
#pragma unroll
            for (int h = 0; h < 2; ++h) {
                const int jl = h * 8 + kq * 2;
                const size_t gidx = (size_t)row * H_SZ + jgbase + jl;
                float2 cold = *reinterpret_cast<const float2*>(&T.cst[gidx]);
                float cn2[2], hn2[2];
#pragma unroll
                for (int e = 0; e < 2; ++e) {
                    const int bofs = wn * 64 + h * 8 + kq * 2 + e;
                    float gi = acc[mi][0 * 2 + h][ri * 2 + e] + T.sbias[bofs];
                    float gf = acc[mi][1 * 2 + h][ri * 2 + e] + T.sbias[bofs + 16];
                    float gc2 = acc[mi][2 * 2 + h][ri * 2 + e] + T.sbias[bofs + 32];
                    float go = acc[mi][3 * 2 + h][ri * 2 + e] + T.sbias[bofs + 48];
                    gi = 1.f / (1.f + __expf(-gi));
                    gf = 1.f / (1.f + __expf(-gf));
                    go = 1.f / (1.f + __expf(-go));
                    gc2 = fmaxf(gc2, 0.f);
                    float co = (e == 0) ? cold.x : cold.y;
                    float cn = gf * co + gi * gc2;
                    cn2[e] = cn;
                    hn2[e] = go * fmaxf(cn, 0.f);
                }
                *reinterpret_cast<float2*>(&T.cst[gidx]) = make_float2(cn2[0], cn2[1]);
                *reinterpret_cast<__half2*>(&T.hout[gidx]) =
                    __floats2half2_rn(hn2[0], hn2[1]);
            }
        }
    }
}

// ---------------------------------------------------------------------------
// Persistent kernel. Interval k runs the continuous stream
// {L2(k-1): 16 chunks, L1(k): 9 chunks} then one ROW-GROUP barrier.
// ---------------------------------------------------------------------------
__global__ void __launch_bounds__(256, 2)
lstm_persistent(const float* __restrict__ Wd,
                const float* __restrict__ bd,
                float* __restrict__ out)
{
    extern __shared__ char dynraw[];
    __shared__ float s_b1[128], s_b2[128];

    const int tid = threadIdx.x;
    const int bid = blockIdx.x;
    const int cbI = bid & 15;
    const int gI  = bid >> 4;
    const int rb  = gI * 128;
    const int cb  = cbI * 128;
    const uint32_t base = smem_u32(dynraw);

    if (tid < 128) {
        s_b1[tid] = g_bp1[cbI * 128 + tid];
        s_b2[tid] = g_bp2[cbI * 128 + tid];
    }
    __syncthreads();

    for (int k = 0; k <= T_SZ; ++k) {
        const int n0 = (k >= 1) ? 16 : 0;           // L2 tile at t = k-1
        const int n1 = (k <= T_SZ - 1) ? 9 : 0;     // L1 tile at t = k
        const int ntot = n0 + n1;
        const int t0 = (k >= 1) ? (k - 1) : 0;
        const int t1 = (k <= T_SZ - 1) ? k : 0;

        Tile T0;
        T0.A1 = g_h1[t0 & 1];            T0.sA1 = H_SZ;
        T0.A2 = g_h2[(t0 & 1) ^ 1];
        T0.B1 = g_Wt2;  T0.BK1 = H_SZ;   T0.B2 = g_Ut2;
        T0.NC1 = H_SZ / KC;
        T0.sbias = s_b2; T0.cst = g_c2;  T0.hout = g_h2[t0 & 1];

        Tile T1;
        T1.A1 = g_x16 + (size_t)t1 * F_SZ; T1.sA1 = T_SZ * F_SZ;
        T1.A2 = g_h1[(t1 & 1) ^ 1];
        T1.B1 = g_Wt1;  T1.BK1 = F_SZ;   T1.B2 = g_Ut1;
        T1.NC1 = F_SZ / KC;
        T1.sbias = s_b1; T1.cst = g_c1;  T1.hout = g_h1[t1 & 1];

        auto issue = [&](int j) {
            if (j >= ntot) return;
            const uint32_t st = base + (j % NSTG) * STAGE_BYTES;
            if (j < n0) load_chunk_t(T0, j,      st, tid, rb, cb);
            else        load_chunk_t(T1, j - n0, st, tid, rb, cb);
        };

        // interval prologue: two chunks in flight
        issue(0);
        issue(1);

        if (n0) consume_tile(T0, 0,  16, ntot, issue, base, tid, rb, cbI);
        if (n1) consume_tile(T1, n0,  9, ntot, issue, base, tid, rb, cbI);

        group_bar(gI, (unsigned)(k + 1));
    }

    // ---- Final dense: 8 group-local rows, one warp per row ---------------
    const int lane = tid & 31;
    const int row  = rb + cbI * 8 + (tid >> 5);
    const __half* h2 = g_h2[(T_SZ - 1) & 1];
    float s = 0.f;
#pragma unroll
    for (int j = lane; j < H_SZ; j += 32)
        s += __half2float(h2[(size_t)row * H_SZ + j]) * Wd[j];
#pragma unroll
    for (int o = 16; o; o >>= 1) s += __shfl_xor_sync(0xFFFFFFFFu, s, o);
    if (lane == 0) out[row] = s + bd[0];
}

// ---------------------------------------------------------------------------
extern "C" void kernel_launch(void* const* d_in, const int* in_sizes, int n_in,
                              void* d_out, int out_size)
{
    const float* x  = (const float*)d_in[0];
    const float* W1 = (const float*)d_in[1];
    const float* U1 = (const float*)d_in[2];
    const float* b1 = (const float*)d_in[3];
    const float* W2 = (const float*)d_in[4];
    const float* U2 = (const float*)d_in[5];
    const float* b2 = (const float*)d_in[6];
    const float* Wd = (const float*)d_in[7];
    const float* bd = (const float*)d_in[8];
    float* out = (float*)d_out;
    (void)in_sizes; (void)n_in; (void)out_size;

    cudaFuncSetAttribute(lstm_persistent,
                         cudaFuncAttributeMaxDynamicSharedMemorySize, SMEM_DYN);

    init_state_kernel<<<(B_SZ * H_SZ + 255) / 256, 256>>>();
    convert_x<<<B_SZ * T_SZ * F_SZ / 256, 256>>>(x);
    transpose_wu<<<2048 * 64 / 256, 256>>>(W1, 64, 0);
    transpose_wu<<<2048 * 512 / 256, 256>>>(U1, 512, 1);
    transpose_wu<<<2048 * 512 / 256, 256>>>(W2, 512, 2);
    transpose_wu<<<2048 * 512 / 256, 256>>>(U2, 512, 3);
    permute_bias<<<8, 256>>>(b1, 0);
    permute_bias<<<8, 256>>>(b2, 1);

    lstm_persistent<<<NCTA, 256, SMEM_DYN>>>(Wd, bd, out);
}